// round 4
// baseline (speedup 1.0000x reference)
#include <cuda_runtime.h>

#define BB 64
#define HH 56
#define WW 56
#define CC 256
#define COUT 64
#define ROUTES 4
#define RW (CC / ROUTES)          // 64 channels per route
#define RCHUNKS 14                // 4 rows per chunk
#define SLOTS 9                   // 3x3 (dh,dw) classes

// per-(batch,chunk) partial patch sums: [BB][RCHUNKS][SLOTS][CC] floats (~8 MB)
__device__ float g_S2[BB * RCHUNKS * SLOTS * CC];
__device__ int   g_route[BB];

__device__ __forceinline__ float4 f4add(float4 a, float4 b) {
    return make_float4(a.x + b.x, a.y + b.y, a.z + b.z, a.w + b.w);
}
__device__ __forceinline__ float4 f4sub(float4 a, float4 b) {
    return make_float4(a.x - b.x, a.y - b.y, a.z - b.z, a.w - b.w);
}

// ---------------------------------------------------------------------------
// K1: streaming patch-sum reduction. Block = (batch, 4-row chunk), 512 threads
// = 64 channel-quads x 8 half-row threads (4 rows x 2 halves). Each thread
// sums 14 even-w + 14 odd-w float4s of its half-row and captures edges.
// Reducer lane (rt==0) combines halves + applies h-parity/boundary logic.
// ---------------------------------------------------------------------------
__global__ __launch_bounds__(512) void patch_sums_kernel(const float* __restrict__ in) {
    const int b     = blockIdx.x;
    const int chunk = blockIdx.y;
    const int q     = threadIdx.x & 63;   // channel quad 0..63
    const int rt    = threadIdx.x >> 6;   // 0..7
    const int r     = rt >> 1;            // row within chunk 0..3
    const int ht    = rt & 1;             // half 0: w in [0,28), half 1: w in [28,56)
    const int h     = chunk * 4 + r;

    const float4* row = (const float4*)in
                      + ((size_t)(b * HH + h) * WW) * (CC / 4) + q;

    float4 e = make_float4(0.f, 0.f, 0.f, 0.f);
    float4 o = make_float4(0.f, 0.f, 0.f, 0.f);
    float4 firsta, lasta, lastb;
#pragma unroll
    for (int i = 0; i < 14; i++) {
        const int w = ht * 28 + 2 * i;
        float4 a  = row[(size_t)w * (CC / 4)];
        float4 bb = row[(size_t)(w + 1) * (CC / 4)];
        if (i == 0)  { firsta = a; }
        if (i == 13) { lasta = a; lastb = bb; }
        e = f4add(e, a);
        o = f4add(o, bb);
    }

    __shared__ float4 se[8][64];
    __shared__ float4 so[8][64];
    __shared__ float4 sedge[4][3][64];   // [row][v0 | v54 | v55]
    se[rt][q] = e;
    so[rt][q] = o;
    if (ht == 0) {
        sedge[r][0][q] = firsta;              // v0 (w=0)
    } else {
        sedge[r][1][q] = lasta;               // v54
        sedge[r][2][q] = lastb;               // v55
    }
    __syncthreads();

    if (rt == 0) {
        float4 out[SLOTS];
#pragma unroll
        for (int s = 0; s < SLOTS; s++) out[s] = make_float4(0.f, 0.f, 0.f, 0.f);

#pragma unroll
        for (int r2 = 0; r2 < 4; r2++) {
            const int hh = chunk * 4 + r2;
            const float4 E = f4add(se[2 * r2][q], se[2 * r2 + 1][q]);
            const float4 O = f4add(so[2 * r2][q], so[2 * r2 + 1][q]);
            const float4 W0 = f4sub(E, sedge[r2][1][q]);  // even w in [0,52]
            const float4 W1 = f4sub(O, sedge[r2][2][q]);  // odd  w in [1,53]
            const float4 W2 = f4sub(E, sedge[r2][0][q]);  // even w in [2,54]
            if ((hh & 1) == 0) {
                if (hh <= 52) { out[0] = f4add(out[0], W0); out[1] = f4add(out[1], W1); out[2] = f4add(out[2], W2); }
                if (hh >= 2)  { out[6] = f4add(out[6], W0); out[7] = f4add(out[7], W1); out[8] = f4add(out[8], W2); }
            } else {
                if (hh <= 53) { out[3] = f4add(out[3], W0); out[4] = f4add(out[4], W1); out[5] = f4add(out[5], W2); }
            }
        }

        float4* dst = (float4*)g_S2 + ((size_t)(b * RCHUNKS + chunk) * SLOTS) * (CC / 4) + q;
#pragma unroll
        for (int s = 0; s < SLOTS; s++)
            dst[(size_t)s * (CC / 4)] = out[s];
    }
}

// ---------------------------------------------------------------------------
// K2 (merged): one block per batch, 512 threads.
// Stage 1: sum 14 chunk-partials -> sS (2304 floats).
// Stage 2: tiny GEMM sS x conv_w -> pooled(64) via 8 sub-segments of 288.
// Stage 3: dense(4) + argmax -> route (and logits output).
// ---------------------------------------------------------------------------
__global__ __launch_bounds__(512) void pooled_route_kernel(const float* __restrict__ conv_w,
                                                           const float* __restrict__ conv_b,
                                                           const float* __restrict__ fc_w,
                                                           const float* __restrict__ fc_b,
                                                           float* __restrict__ out_logits) {
    const int b   = blockIdx.x;
    const int tid = threadIdx.x;

    __shared__ __align__(16) float sS[SLOTS * CC];   // 2304
    for (int i = tid; i < SLOTS * CC / 4; i += 512) {
        float4 s = make_float4(0.f, 0.f, 0.f, 0.f);
#pragma unroll
        for (int k = 0; k < RCHUNKS; k++) {
            const float4* src = (const float4*)g_S2
                              + (size_t)(b * RCHUNKS + k) * (SLOTS * CC / 4) + i;
            s = f4add(s, *src);
        }
        ((float4*)sS)[i] = s;
    }
    __syncthreads();

    const int o   = tid & 63;
    const int sub = tid >> 6;          // 0..7
    const int j0  = sub * 288;

    float acc = 0.f;
#pragma unroll 8
    for (int j = 0; j < 288; j++)
        acc = fmaf(sS[j0 + j], conv_w[(size_t)(j0 + j) * COUT + o], acc);

    __shared__ float part[8][COUT];
    part[sub][o] = acc;
    __syncthreads();

    __shared__ float sp[COUT];
    __shared__ float slog[ROUTES];
    if (tid < COUT) {
        float p = 0.f;
#pragma unroll
        for (int s = 0; s < 8; s++) p += part[s][tid];
        sp[tid] = p * (1.0f / 729.0f) + conv_b[tid];
    }
    __syncthreads();

    if (tid < ROUTES) {
        float l = fc_b[tid];
#pragma unroll
        for (int j = 0; j < COUT; j++)
            l = fmaf(sp[j], fc_w[j * ROUTES + tid], l);
        slog[tid] = l;
        out_logits[b * ROUTES + tid] = l;
    }
    __syncthreads();

    if (tid == 0) {
        float best = slog[0];
        int br = 0;
#pragma unroll
        for (int r = 1; r < ROUTES; r++)
            if (slog[r] > best) { best = slog[r]; br = r; }  // first-max == argmax
        g_route[b] = br;
    }
}

// ---------------------------------------------------------------------------
// K3: routed channel-group gather. Block = (batch, 112-pixel tile),
// 7 independent float4 copies per thread, streaming stores.
// ---------------------------------------------------------------------------
__global__ __launch_bounds__(256) void gather_kernel(const float4* __restrict__ in4,
                                                     float4* __restrict__ out4) {
    const int b = blockIdx.x;
    const int r = g_route[b];
    const size_t base_pix = (size_t)b * (HH * WW) + (size_t)blockIdx.y * 112;
    const float4* src = in4 + base_pix * (CC / 4) + r * (RW / 4);
    float4* dst = out4 + base_pix * (RW / 4);

    const int t = threadIdx.x;
#pragma unroll
    for (int k = 0; k < 7; k++) {
        const int item = t + k * 256;      // 0..1791 = 112 pixels x 16 float4
        const int p = item >> 4;
        const int j = item & 15;
        float4 v = src[(size_t)p * (CC / 4) + j];
        __stcs(&dst[item], v);
    }
}

// ---------------------------------------------------------------------------
extern "C" void kernel_launch(void* const* d_in, const int* in_sizes, int n_in,
                              void* d_out, int out_size) {
    const float* in     = (const float*)d_in[0];
    const float* conv_w = (const float*)d_in[1];
    const float* conv_b = (const float*)d_in[2];
    const float* fc_w   = (const float*)d_in[3];
    const float* fc_b   = (const float*)d_in[4];

    float* out        = (float*)d_out;
    float* out_logits = out + (size_t)BB * HH * WW * RW;  // x first, then logits

    patch_sums_kernel<<<dim3(BB, RCHUNKS), 512>>>(in);
    pooled_route_kernel<<<BB, 512>>>(conv_w, conv_b, fc_w, fc_b, out_logits);
    gather_kernel<<<dim3(BB, HH * WW / 112), 256>>>((const float4*)in, (float4*)out);
}